// round 7
// baseline (speedup 1.0000x reference)
#include <cuda_runtime.h>
#include <math.h>
#include <stdint.h>

#define B_ 64
#define T_ 512
#define H_ 1024
#define C_ 21

typedef unsigned long long ull;

__device__ __forceinline__ ull pk2(float lo, float hi) {
    ull r; asm("mov.b64 %0, {%1, %2};" : "=l"(r) : "f"(lo), "f"(hi)); return r;
}
__device__ __forceinline__ void upk2(ull v, float& lo, float& hi) {
    asm("mov.b64 {%0, %1}, %2;" : "=f"(lo), "=f"(hi) : "l"(v));
}
__device__ __forceinline__ ull fma2(ull a, ull b, ull c) {
    ull d; asm("fma.rn.f32x2 %0, %1, %2, %3;" : "=l"(d) : "l"(a), "l"(b), "l"(c)); return d;
}
__device__ __forceinline__ ull mul2(ull a, ull b) {
    ull d; asm("mul.rn.f32x2 %0, %1, %2;" : "=l"(d) : "l"(a), "l"(b)); return d;
}
__device__ __forceinline__ ull add2(ull a, ull b) {
    ull d; asm("add.rn.f32x2 %0, %1, %2;" : "=l"(d) : "l"(a), "l"(b)); return d;
}

// ================= GEMM: emissions = hs @ W + b =================
// 128 persistent blocks, 16 warps (512 thr), 4 groups/block exactly.
// Warp w owns h-slice [w*64, w*64+64), consumed as 2 chunks of 32 h.
// Group = 64 rows. RPT=4 (rows rbase, +16, +32, +48), half-warp class split.
// Pair tile (full-lane xor swizzle): per hh, two LDS.64 feed 4 rows;
// W = 3 LDS.128 per hh -> 24 f32x2 FMA per ~8 wavefronts.

#define GEMM_GRID 128
#define GNT 512
#define NWARP 16
#define GROUP_ROWS 64
#define NGROUPS ((B_ * T_) / GROUP_ROWS)   // 512
#define WPAD 24
#define TWORDS 2048                        // per-warp tile: 32 hh x 64 cols

__global__ void __launch_bounds__(GNT, 1)
gemm_kernel(const float* __restrict__ hs, const float* __restrict__ W,
            const float* __restrict__ bias, float* __restrict__ out)
{
    extern __shared__ float smem[];
    float* sW     = smem;                    // 24576 fl (96 KB)
    float* sStage = sW + H_ * WPAD;          // 16*2048 fl (128 KB)

    for (int idx = threadIdx.x; idx < H_ * WPAD; idx += GNT) {
        int h = idx / WPAD;
        int j = idx - h * WPAD;
        sW[idx] = (j < C_) ? W[h * C_ + j] : 0.f;
    }
    __syncthreads();

    const int warp  = threadIdx.x >> 5;
    const int lane  = threadIdx.x & 31;
    const int half  = lane >> 4;
    const int rbase = lane & 15;
    float* tile = sStage + warp * TWORDS;
    const int hwarp = warp * 64;

    for (int g = blockIdx.x; g < NGROUPS; g += GEMM_GRID) {
        const int row0 = g * GROUP_ROWS;

        ull acc2[4][6];
#pragma unroll
        for (int rp = 0; rp < 4; rp++)
#pragma unroll
            for (int p = 0; p < 6; p++) acc2[rp][p] = 0ull;

#pragma unroll
        for (int ch = 0; ch < 2; ch++) {
            // stage 64 rows x 32 h; write swizzle = full 5-bit lane xor
            {
                const float* src = hs + (size_t)row0 * H_ + hwarp + ch * 32 + lane;
#pragma unroll 16
                for (int r = 0; r < GROUP_ROWS; r++) {
                    const int plane = r >> 5;
                    const int pcol  = ((r & 15) << 1) | ((r >> 4) & 1);
                    tile[(lane << 6) + (plane << 5) + (pcol ^ lane)] =
                        src[(size_t)r * H_];
                }
            }
            __syncwarp();

            const float* wb = sW + (size_t)(hwarp + ch * 32) * WPAD + half * 12;
#pragma unroll 8
            for (int hh = 0; hh < 32; hh++) {
                const ulonglong2 qa = *(const ulonglong2*)(wb + hh * WPAD);
                const ulonglong2 qb = *(const ulonglong2*)(wb + hh * WPAD + 4);
                const ulonglong2 qc = *(const ulonglong2*)(wb + hh * WPAD + 8);
                const int cidx = ((rbase << 1) ^ (hh & 30));
                const float2 xa = *(const float2*)&tile[(hh << 6) + cidx];
                const float2 xb = *(const float2*)&tile[(hh << 6) + 32 + cidx];
                // parity swap (compile-time under unroll): odd hh swaps pair order
                const float x0 = (hh & 1) ? xa.y : xa.x;   // row rbase
                const float x1 = (hh & 1) ? xa.x : xa.y;   // row rbase+16
                const float x2 = (hh & 1) ? xb.y : xb.x;   // row rbase+32
                const float x3 = (hh & 1) ? xb.x : xb.y;   // row rbase+48
                const ull xx0 = pk2(x0, x0);
                const ull xx1 = pk2(x1, x1);
                const ull xx2 = pk2(x2, x2);
                const ull xx3 = pk2(x3, x3);
                acc2[0][0] = fma2(xx0, qa.x, acc2[0][0]);
                acc2[1][0] = fma2(xx1, qa.x, acc2[1][0]);
                acc2[2][0] = fma2(xx2, qa.x, acc2[2][0]);
                acc2[3][0] = fma2(xx3, qa.x, acc2[3][0]);
                acc2[0][1] = fma2(xx0, qa.y, acc2[0][1]);
                acc2[1][1] = fma2(xx1, qa.y, acc2[1][1]);
                acc2[2][1] = fma2(xx2, qa.y, acc2[2][1]);
                acc2[3][1] = fma2(xx3, qa.y, acc2[3][1]);
                acc2[0][2] = fma2(xx0, qb.x, acc2[0][2]);
                acc2[1][2] = fma2(xx1, qb.x, acc2[1][2]);
                acc2[2][2] = fma2(xx2, qb.x, acc2[2][2]);
                acc2[3][2] = fma2(xx3, qb.x, acc2[3][2]);
                acc2[0][3] = fma2(xx0, qb.y, acc2[0][3]);
                acc2[1][3] = fma2(xx1, qb.y, acc2[1][3]);
                acc2[2][3] = fma2(xx2, qb.y, acc2[2][3]);
                acc2[3][3] = fma2(xx3, qb.y, acc2[3][3]);
                acc2[0][4] = fma2(xx0, qc.x, acc2[0][4]);
                acc2[1][4] = fma2(xx1, qc.x, acc2[1][4]);
                acc2[2][4] = fma2(xx2, qc.x, acc2[2][4]);
                acc2[3][4] = fma2(xx3, qc.x, acc2[3][4]);
                acc2[0][5] = fma2(xx0, qc.y, acc2[0][5]);
                acc2[1][5] = fma2(xx1, qc.y, acc2[1][5]);
                acc2[2][5] = fma2(xx2, qc.y, acc2[2][5]);
                acc2[3][5] = fma2(xx3, qc.y, acc2[3][5]);
            }
            __syncwarp();
        }

        // partials: warp's own tile reused as red buffer (row*24 + class)
        {
            float* red = tile;
#pragma unroll
            for (int rp = 0; rp < 4; rp++) {
                const int row = rbase + 16 * rp;
#pragma unroll
                for (int p = 0; p < 6; p++) {
                    float lo_, hi_;
                    upk2(acc2[rp][p], lo_, hi_);
                    *(float2*)&red[row * 24 + half * 12 + 2 * p] =
                        make_float2(lo_, hi_);
                }
            }
        }
        __syncthreads();

        const int NOUT = GROUP_ROWS * C_;   // 1344
        for (int idx = threadIdx.x; idx < NOUT; idx += GNT) {
            const int row = idx / C_;
            const int c   = idx - row * C_;
            float s = 0.f;
#pragma unroll
            for (int w2 = 0; w2 < NWARP; w2++)
                s += sStage[w2 * TWORDS + row * 24 + c];
            out[(size_t)row0 * C_ + idx] = s + bias[c];
        }
        __syncthreads();
    }
}

// ================= CRF =================
// lenk: per-sequence length. crf2: 32 blocks; each handles the two
// sequences of adjacent length-rank (pair longest with next-longest) and
// runs BOTH forward recursions interleaved in warp 0 (independent chains
// hide each other's shfl latency); solo tail for the longer one.

__device__ float g_llh[B_];
__device__ int   g_L[B_];

__global__ void __launch_bounds__(32, 1)
lenk(const int* __restrict__ att, const int* __restrict__ labels)
{
    const int b = blockIdx.x;
    const int lane = threadIdx.x;
    const int* tag = labels + b * T_;
    const int* mrow = att + b * T_;
    int cnt = 0;
    for (int t = lane; t < T_; t += 32) {
        bool mk = (t == 0) ? true : (mrow[t] != 0 && tag[t] != -100);
        cnt += mk ? 1 : 0;
    }
#pragma unroll
    for (int o = 16; o; o >>= 1) cnt += __shfl_xor_sync(0xffffffffu, cnt, o);
    if (lane == 0) g_L[b] = cnt;
}

__global__ void __launch_bounds__(128, 1)
crf_kernel(const float* __restrict__ em_all, const float* __restrict__ trans,
           const float* __restrict__ startT, const float* __restrict__ endT,
           const int* __restrict__ labels)
{
    extern __shared__ float sE[];          // [2][T_*C_]
    float* sEA = sE;
    float* sEB = sE + T_ * C_;
    __shared__ int sMap[B_];
    __shared__ float sNumA, sNumB;

    const int tid = threadIdx.x;
    const int warp = tid >> 5;
    const int lane = tid & 31;
    const unsigned FULL = 0xffffffffu;

    // rank sequences by length (desc), pair (2p, 2p+1)
    if (tid < B_) {
        const int key = (g_L[tid] << 6) | tid;
        int rank = 0;
        for (int i = 0; i < B_; i++)
            rank += (((g_L[i] << 6) | i) > key) ? 1 : 0;
        sMap[rank] = tid;
    }
    __syncthreads();
    const int bA = sMap[2 * blockIdx.x];
    const int bB = sMap[2 * blockIdx.x + 1];
    const int LA = g_L[bA];                // LA >= LB
    const int LB = g_L[bB];
    const float* emA = em_all + (size_t)bA * T_ * C_;
    const float* emB = em_all + (size_t)bB * T_ * C_;

    // stage exp(em) for both (threads 0-63 -> A, 64-127 -> B)
    {
        const float* em = (tid < 64) ? emA : emB;
        float* dst = (tid < 64) ? sEA : sEB;
        const int Ls = (tid < 64) ? LA : LB;
        const int tt = tid & 63;
        const float4* em4 = (const float4*)em;
        float4* d4 = (float4*)dst;
        const int n4 = (Ls * C_ + 3) >> 2;
        for (int i = tt; i < n4; i += 64) {
            float4 v = em4[i];
            v.x = __expf(v.x); v.y = __expf(v.y);
            v.z = __expf(v.z); v.w = __expf(v.w);
            d4[i] = v;
        }
    }
    __syncthreads();

    if (warp == 1 || warp == 2) {          // numerators
        const int bS = (warp == 1) ? bA : bB;
        const int Ls = (warp == 1) ? LA : LB;
        const float* em = (warp == 1) ? emA : emB;
        const int* tag = labels + bS * T_;
        float part = 0.f;
        for (int t = 1 + lane; t < Ls; t += 32)
            part += trans[tag[t - 1] * C_ + tag[t]] + em[t * C_ + tag[t]];
#pragma unroll
        for (int o = 16; o; o >>= 1) part += __shfl_xor_sync(FULL, part, o);
        if (lane == 0) {
            float num = part + startT[tag[0]] + em[tag[0]] + endT[tag[Ls - 1]];
            if (warp == 1) sNumA = num; else sNumB = num;
        }
    }

    float logZA = 0.f, logZB = 0.f;
    if (warp == 0) {
        const int j = (lane < C_) ? lane : (C_ - 1);

        ull E2[11];
#pragma unroll
        for (int k = 0; k < 10; k++)
            E2[k] = pk2(__expf(trans[(2 * k) * C_ + j]),
                        __expf(trans[(2 * k + 1) * C_ + j]));
        E2[10] = pk2(__expf(trans[20 * C_ + j]), 0.f);
        const float eend = (lane < C_) ? __expf(endT[j]) : 0.f;
        const float est = __expf(startT[j]);

        ull vA[11], vB[11];
        float accA, accB;
        {
            float wA = est * sEA[j];
            float wB = est * sEB[j];
#pragma unroll
            for (int k = 0; k < 10; k++) {
                vA[k] = pk2(__shfl_sync(FULL, wA, 2 * k),
                            __shfl_sync(FULL, wA, 2 * k + 1));
                vB[k] = pk2(__shfl_sync(FULL, wB, 2 * k),
                            __shfl_sync(FULL, wB, 2 * k + 1));
            }
            vA[10] = pk2(__shfl_sync(FULL, wA, 20), 0.f);
            vB[10] = pk2(__shfl_sync(FULL, wB, 20), 0.f);
            float w0A = __shfl_sync(FULL, wA, 0);
            float w0B = __shfl_sync(FULL, wB, 0);
            accA = __logf(w0A);
            accB = __logf(w0B);
            const ull rA = pk2(__fdividef(1.f, w0A), __fdividef(1.f, w0A));
            const ull rB = pk2(__fdividef(1.f, w0B), __fdividef(1.f, w0B));
#pragma unroll
            for (int k = 0; k < 11; k++) { vA[k] = mul2(vA[k], rA);
                                           vB[k] = mul2(vB[k], rB); }
        }

#define DUAL_STEP(TIDX, RENORM) do {                                         \
        const float eetA = sEA[(TIDX) * C_ + j];                             \
        const float eetB = sEB[(TIDX) * C_ + j];                             \
        ull a0 = mul2(E2[0], vA[0]), b0 = mul2(E2[0], vB[0]);                \
        ull a1 = mul2(E2[1], vA[1]), b1 = mul2(E2[1], vB[1]);                \
        ull a2 = mul2(E2[2], vA[2]), b2 = mul2(E2[2], vB[2]);                \
        a0 = fma2(E2[3], vA[3], a0);  b0 = fma2(E2[3], vB[3], b0);           \
        a1 = fma2(E2[4], vA[4], a1);  b1 = fma2(E2[4], vB[4], b1);           \
        a2 = fma2(E2[5], vA[5], a2);  b2 = fma2(E2[5], vB[5], b2);           \
        a0 = fma2(E2[6], vA[6], a0);  b0 = fma2(E2[6], vB[6], b0);           \
        a1 = fma2(E2[7], vA[7], a1);  b1 = fma2(E2[7], vB[7], b1);           \
        a2 = fma2(E2[8], vA[8], a2);  b2 = fma2(E2[8], vB[8], b2);           \
        a0 = fma2(E2[9], vA[9], a0);  b0 = fma2(E2[9], vB[9], b0);           \
        a1 = fma2(E2[10], vA[10], a1); b1 = fma2(E2[10], vB[10], b1);        \
        ull sA2 = add2(add2(a0, a1), a2);                                    \
        ull sB2 = add2(add2(b0, b1), b2);                                    \
        float alo, ahi, blo, bhi;                                            \
        upk2(sA2, alo, ahi); upk2(sB2, blo, bhi);                            \
        float uA = (alo + ahi) * eetA;                                       \
        float uB = (blo + bhi) * eetB;                                       \
        if (RENORM) {                                                        \
            float cA = __shfl_sync(FULL, uA, 0);                             \
            float cB = __shfl_sync(FULL, uB, 0);                             \
            accA += __logf(cA); accB += __logf(cB);                          \
            uA *= __fdividef(1.f, cA); uB *= __fdividef(1.f, cB);            \
        }                                                                    \
        _Pragma("unroll")                                                    \
        for (int k = 0; k < 10; k++) {                                       \
            vA[k] = pk2(__shfl_sync(FULL, uA, 2 * k),                        \
                        __shfl_sync(FULL, uA, 2 * k + 1));                   \
            vB[k] = pk2(__shfl_sync(FULL, uB, 2 * k),                        \
                        __shfl_sync(FULL, uB, 2 * k + 1));                   \
        }                                                                    \
        vA[10] = pk2(__shfl_sync(FULL, uA, 20), 0.f);                        \
        vB[10] = pk2(__shfl_sync(FULL, uB, 20), 0.f);                        \
    } while (0)

#define SOLO_STEP(TIDX, RENORM) do {                                         \
        const float eetA = sEA[(TIDX) * C_ + j];                             \
        ull a0 = mul2(E2[0], vA[0]);                                         \
        ull a1 = mul2(E2[1], vA[1]);                                         \
        ull a2 = mul2(E2[2], vA[2]);                                         \
        a0 = fma2(E2[3], vA[3], a0);                                         \
        a1 = fma2(E2[4], vA[4], a1);                                         \
        a2 = fma2(E2[5], vA[5], a2);                                         \
        a0 = fma2(E2[6], vA[6], a0);                                         \
        a1 = fma2(E2[7], vA[7], a1);                                         \
        a2 = fma2(E2[8], vA[8], a2);                                         \
        a0 = fma2(E2[9], vA[9], a0);                                         \
        a1 = fma2(E2[10], vA[10], a1);                                       \
        ull sA2 = add2(add2(a0, a1), a2);                                    \
        float alo, ahi; upk2(sA2, alo, ahi);                                 \
        float uA = (alo + ahi) * eetA;                                       \
        if (RENORM) {                                                        \
            float cA = __shfl_sync(FULL, uA, 0);                             \
            accA += __logf(cA);                                              \
            uA *= __fdividef(1.f, cA);                                       \
        }                                                                    \
        _Pragma("unroll")                                                    \
        for (int k = 0; k < 10; k++)                                         \
            vA[k] = pk2(__shfl_sync(FULL, uA, 2 * k),                        \
                        __shfl_sync(FULL, uA, 2 * k + 1));                   \
        vA[10] = pk2(__shfl_sync(FULL, uA, 20), 0.f);                        \
    } while (0)

        int t = 1;
        const int nJ = (LB - 1) >> 3;
        for (int it = 0; it < nJ; it++) {
            DUAL_STEP(t + 0, 0);
            DUAL_STEP(t + 1, 0);
            DUAL_STEP(t + 2, 0);
            DUAL_STEP(t + 3, 0);
            DUAL_STEP(t + 4, 0);
            DUAL_STEP(t + 5, 0);
            DUAL_STEP(t + 6, 0);
            DUAL_STEP(t + 7, 1);
            t += 8;
        }
        for (; t < LB; t++) DUAL_STEP(t, 1);      // joint tail (renorm each)
        const int nS = (LA - t) >> 3;
        for (int it = 0; it < nS; it++) {
            SOLO_STEP(t + 0, 0);
            SOLO_STEP(t + 1, 0);
            SOLO_STEP(t + 2, 0);
            SOLO_STEP(t + 3, 0);
            SOLO_STEP(t + 4, 0);
            SOLO_STEP(t + 5, 0);
            SOLO_STEP(t + 6, 0);
            SOLO_STEP(t + 7, 1);
            t += 8;
        }
        for (; t < LA; t++) SOLO_STEP(t, 1);      // solo tail

        // z = sum_j v_j * exp(end_j), per sequence
        float vloA, vhiA, vloB, vhiB;
        upk2(vA[j >> 1], vloA, vhiA);
        upk2(vB[j >> 1], vloB, vhiB);
        float zA = ((j & 1) ? vhiA : vloA) * eend;
        float zB = ((j & 1) ? vhiB : vloB) * eend;
#pragma unroll
        for (int o = 16; o; o >>= 1) {
            zA += __shfl_xor_sync(FULL, zA, o);
            zB += __shfl_xor_sync(FULL, zB, o);
        }
        logZA = accA + __logf(zA);
        logZB = accB + __logf(zB);
    }

    __syncthreads();
    if (tid == 0) {
        g_llh[bA] = sNumA - logZA;
        g_llh[bB] = sNumB - logZB;
    }
}

__global__ void reduce_kernel(float* __restrict__ out_loss)
{
    const int lane = threadIdx.x;   // 64 threads
    __shared__ float sp[2];
    float v = g_llh[lane];
#pragma unroll
    for (int o = 16; o; o >>= 1) v += __shfl_xor_sync(0xffffffffu, v, o);
    if ((lane & 31) == 0) sp[lane >> 5] = v;
    __syncthreads();
    if (lane == 0) out_loss[0] = -(sp[0] + sp[1]) / (float)B_;
}

// ---------------- launch ----------------

extern "C" void kernel_launch(void* const* d_in, const int* in_sizes, int n_in,
                              void* d_out, int out_size)
{
    const float* hs     = (const float*)d_in[0];
    const float* W      = (const float*)d_in[1];
    const float* bias   = (const float*)d_in[2];
    const float* trans  = (const float*)d_in[3];
    const float* startT = (const float*)d_in[4];
    const float* endT   = (const float*)d_in[5];
    const int*   att    = (const int*)d_in[6];
    const int*   labels = (const int*)d_in[7];
    float* out = (float*)d_out;

    const size_t gsmem = (size_t)(H_ * WPAD + NWARP * TWORDS) * sizeof(float);
    cudaFuncSetAttribute(gemm_kernel, cudaFuncAttributeMaxDynamicSharedMemorySize, (int)gsmem);
    const size_t csmem = (size_t)(2 * T_ * C_) * sizeof(float);
    cudaFuncSetAttribute(crf_kernel, cudaFuncAttributeMaxDynamicSharedMemorySize, (int)csmem);

    lenk<<<B_, 32>>>(att, labels);
    gemm_kernel<<<GEMM_GRID, GNT, gsmem>>>(hs, W, bias, out);
    crf_kernel<<<B_ / 2, 128, csmem>>>(out, trans, startT, endT, labels);
    reduce_kernel<<<1, 64>>>(out + (out_size - 1));
}

// round 9
// speedup vs baseline: 1.4914x; 1.4914x over previous
#include <cuda_runtime.h>
#include <cuda_bf16.h>
#include <math.h>
#include <stdint.h>

#define B_ 64
#define T_ 512
#define H_ 1024
#define C_ 21

typedef unsigned long long ull;

// ---------------- f32x2 helpers (CRF) ----------------
__device__ __forceinline__ ull pk2(float lo, float hi) {
    ull r; asm("mov.b64 %0, {%1, %2};" : "=l"(r) : "f"(lo), "f"(hi)); return r;
}
__device__ __forceinline__ void upk2(ull v, float& lo, float& hi) {
    asm("mov.b64 {%0, %1}, %2;" : "=f"(lo), "=f"(hi) : "l"(v));
}
__device__ __forceinline__ ull fma2(ull a, ull b, ull c) {
    ull d; asm("fma.rn.f32x2 %0, %1, %2, %3;" : "=l"(d) : "l"(a), "l"(b), "l"(c)); return d;
}
__device__ __forceinline__ ull mul2(ull a, ull b) {
    ull d; asm("mul.rn.f32x2 %0, %1, %2;" : "=l"(d) : "l"(a), "l"(b)); return d;
}
__device__ __forceinline__ ull add2(ull a, ull b) {
    ull d; asm("add.rn.f32x2 %0, %1, %2;" : "=l"(d) : "l"(a), "l"(b)); return d;
}

// ================= GEMM: emissions = hs @ W + b via mma.sync =================
// 256 CTAs x 256 thr (8 warps). Warp owns 16 rows x K=1024.
// A: direct LDG float2 per lane per k-step (each element read once),
//    truncation-split to bf16 hi/lo in registers.
// B: W^T staged once per CTA in smem as bf16 hi/lo [24][1032] (n-major,
//    pad 1032 -> word stride 516 = 4 mod 32 -> conflict-free frag reads).
// 3 split products per n-group: ahi*bhi + ahi*blo + alo*bhi.

#define KPAD 1032
#define SMEM_B_BYTES (2 * 24 * KPAD * 2)   // 99072

__device__ __forceinline__ void mma_bf16(float* d,
                                         uint32_t a0, uint32_t a1,
                                         uint32_t a2, uint32_t a3,
                                         uint32_t b0, uint32_t b1) {
    asm volatile(
        "mma.sync.aligned.m16n8k16.row.col.f32.bf16.bf16.f32 "
        "{%0,%1,%2,%3}, {%4,%5,%6,%7}, {%8,%9}, {%0,%1,%2,%3};"
        : "+f"(d[0]), "+f"(d[1]), "+f"(d[2]), "+f"(d[3])
        : "r"(a0), "r"(a1), "r"(a2), "r"(a3), "r"(b0), "r"(b1));
}

// split float2 -> (hi bf16x2 [trunc], lo bf16x2 [rn of exact residual])
__device__ __forceinline__ void split2(float2 f, uint32_t& hi, uint32_t& lo) {
    const uint32_t ux = __float_as_uint(f.x);
    const uint32_t uy = __float_as_uint(f.y);
    hi = __byte_perm(ux, uy, 0x7632);
    const float lx = f.x - __uint_as_float(ux & 0xffff0000u);
    const float ly = f.y - __uint_as_float(uy & 0xffff0000u);
    asm("cvt.rn.bf16x2.f32 %0, %1, %2;" : "=r"(lo) : "f"(ly), "f"(lx));
}

__global__ void __launch_bounds__(256, 2)
gemm_mma(const float* __restrict__ hs, const float* __restrict__ W,
         const float* __restrict__ bias, float* __restrict__ out)
{
    extern __shared__ char smem[];
    unsigned short* sBhi = (unsigned short*)smem;             // [24][KPAD]
    unsigned short* sBlo = sBhi + 24 * KPAD;

    const int tid  = threadIdx.x;
    const int wid  = tid >> 5;
    const int lane = tid & 31;
    const int g    = lane >> 2;       // 0..7
    const int tg   = lane & 3;        // 0..3

    // ---- stage W^T bf16 hi/lo (coalesced W read) ----
    for (int i = tid; i < H_ * C_; i += 256) {
        const int k = i / C_;
        const int n = i - k * C_;
        const uint32_t u = __float_as_uint(W[i]);
        const float lo = __uint_as_float(u) - __uint_as_float(u & 0xffff0000u);
        sBhi[n * KPAD + k] = (unsigned short)(u >> 16);
        unsigned short ls;
        asm("{ .reg .b16 t; cvt.rn.bf16.f32 t, %1; mov.b16 %0, t; }"
            : "=h"(ls) : "f"(lo));
        sBlo[n * KPAD + k] = ls;
    }
    // zero pad classes 21..23
    for (int i = tid; i < 3 * H_; i += 256) {
        const int n = 21 + (i >> 10);
        const int k = i & 1023;
        sBhi[n * KPAD + k] = 0;
        sBlo[n * KPAD + k] = 0;
    }
    __syncthreads();

    const int row0w = blockIdx.x * 128 + wid * 16;
    const int r0 = row0w + g;
    const int r1 = r0 + 8;
    const float* pa0 = hs + (size_t)r0 * H_ + tg * 2;
    const float* pa1 = hs + (size_t)r1 * H_ + tg * 2;
    const unsigned short* bk = sBhi;   // indexed later

    float acc[3][4];
#pragma unroll
    for (int no = 0; no < 3; no++)
#pragma unroll
        for (int p = 0; p < 4; p++) acc[no][p] = 0.f;

#pragma unroll 4
    for (int ks = 0; ks < 64; ks++) {
        const int k0 = ks * 16;
        // A fragments (rows g, g+8; k halves lo/hi)
        const float2 f00 = *(const float2*)(pa0 + k0);
        const float2 f10 = *(const float2*)(pa1 + k0);
        const float2 f01 = *(const float2*)(pa0 + k0 + 8);
        const float2 f11 = *(const float2*)(pa1 + k0 + 8);
        uint32_t ah0, al0, ah1, al1, ah2, al2, ah3, al3;
        split2(f00, ah0, al0);
        split2(f10, ah1, al1);
        split2(f01, ah2, al2);
        split2(f11, ah3, al3);

        const int kb = k0 + tg * 2;
#pragma unroll
        for (int no = 0; no < 3; no++) {
            const int n = no * 8 + g;
            const unsigned short* ph = sBhi + n * KPAD + kb;
            const unsigned short* pl = sBlo + n * KPAD + kb;
            const uint32_t bh0 = *(const uint32_t*)(ph);
            const uint32_t bh1 = *(const uint32_t*)(ph + 8);
            const uint32_t bl0 = *(const uint32_t*)(pl);
            const uint32_t bl1 = *(const uint32_t*)(pl + 8);
            mma_bf16(acc[no], ah0, ah1, ah2, ah3, bh0, bh1);
            mma_bf16(acc[no], ah0, ah1, ah2, ah3, bl0, bl1);
            mma_bf16(acc[no], al0, al1, al2, al3, bh0, bh1);
        }
    }
    (void)bk;

    // ---- epilogue: scalar stores (+bias); cols >= 21 discarded ----
    float* o0 = out + (size_t)r0 * C_;
    float* o1 = out + (size_t)r1 * C_;
#pragma unroll
    for (int no = 0; no < 3; no++) {
        const int c0 = no * 8 + tg * 2;
        const int c1 = c0 + 1;
        if (c0 < C_) {
            const float bz = bias[c0];
            o0[c0] = acc[no][0] + bz;
            o1[c0] = acc[no][2] + bz;
        }
        if (c1 < C_) {
            const float bz = bias[c1];
            o0[c1] = acc[no][1] + bz;
            o1[c1] = acc[no][3] + bz;
        }
    }
}

// ============ CRF: per-sequence forward, packed-f32x2 registers (R6) ============

__device__ float g_llh[B_];

__global__ void __launch_bounds__(128, 1)
crf_kernel(const float* __restrict__ em_all, const float* __restrict__ trans,
           const float* __restrict__ startT, const float* __restrict__ endT,
           const int* __restrict__ att, const int* __restrict__ labels)
{
    __shared__ __align__(16) float sEexp[T_ * C_];
    __shared__ float sNum;

    const int b = blockIdx.x;
    const int tid = threadIdx.x;
    const int warp = tid >> 5;
    const int lane = tid & 31;
    const float* em = em_all + (size_t)b * T_ * C_;
    const int* tag = labels + b * T_;
    const int* mrow = att + b * T_;
    const unsigned FULL = 0xffffffffu;

    int cnt = 0;
    for (int t = lane; t < T_; t += 32) {
        bool mk = (t == 0) ? true : (mrow[t] != 0 && tag[t] != -100);
        cnt += mk ? 1 : 0;
    }
#pragma unroll
    for (int o = 16; o; o >>= 1) cnt += __shfl_xor_sync(FULL, cnt, o);
    const int L = cnt;

    {
        const float4* em4 = (const float4*)em;
        float4* se4 = (float4*)sEexp;
        const int n4 = (L * C_ + 3) >> 2;
        for (int i = tid; i < n4; i += 128) {
            float4 v = em4[i];
            v.x = __expf(v.x); v.y = __expf(v.y);
            v.z = __expf(v.z); v.w = __expf(v.w);
            se4[i] = v;
        }
    }
    __syncthreads();

    if (warp == 1) {
        float part = 0.f;
        for (int t = 1 + lane; t < L; t += 32)
            part += trans[tag[t - 1] * C_ + tag[t]] + em[t * C_ + tag[t]];
#pragma unroll
        for (int o = 16; o; o >>= 1) part += __shfl_xor_sync(FULL, part, o);
        if (lane == 0)
            sNum = part + startT[tag[0]] + em[tag[0]] + endT[tag[L - 1]];
    }

    float logZ = 0.f;
    if (warp == 0) {
        const int j = (lane < C_) ? lane : (C_ - 1);

        ull E2[11];
#pragma unroll
        for (int k = 0; k < 10; k++)
            E2[k] = pk2(__expf(trans[(2 * k) * C_ + j]),
                        __expf(trans[(2 * k + 1) * C_ + j]));
        E2[10] = pk2(__expf(trans[20 * C_ + j]), 0.f);
        const float eend = (lane < C_) ? __expf(endT[j]) : 0.f;

        float w = __expf(startT[j]) * sEexp[j];
        ull v2[11];
#pragma unroll
        for (int k = 0; k < 10; k++)
            v2[k] = pk2(__shfl_sync(FULL, w, 2 * k),
                        __shfl_sync(FULL, w, 2 * k + 1));
        v2[10] = pk2(__shfl_sync(FULL, w, 20), 0.f);
        float w0 = __shfl_sync(FULL, w, 0);
        float acc = __logf(w0);
        {
            const float rw0 = __fdividef(1.f, w0);
            const ull rr = pk2(rw0, rw0);
#pragma unroll
            for (int k = 0; k < 11; k++) v2[k] = mul2(v2[k], rr);
        }

#define CRF_STEP(TIDX, RENORM) do {                                          \
        const float eet = sEexp[(TIDX) * C_ + j];                            \
        ull ch0 = mul2(E2[0], v2[0]);                                        \
        ull ch1 = mul2(E2[1], v2[1]);                                        \
        ull ch2 = mul2(E2[2], v2[2]);                                        \
        ch0 = fma2(E2[3], v2[3], ch0);                                       \
        ch1 = fma2(E2[4], v2[4], ch1);                                       \
        ch2 = fma2(E2[5], v2[5], ch2);                                       \
        ch0 = fma2(E2[6], v2[6], ch0);                                       \
        ch1 = fma2(E2[7], v2[7], ch1);                                       \
        ch2 = fma2(E2[8], v2[8], ch2);                                       \
        ch0 = fma2(E2[9], v2[9], ch0);                                       \
        ch1 = fma2(E2[10], v2[10], ch1);                                     \
        ull s2 = add2(add2(ch0, ch1), ch2);                                  \
        float slo, shi; upk2(s2, slo, shi);                                  \
        float u = (slo + shi) * eet;                                         \
        if (RENORM) {                                                        \
            float cn = __shfl_sync(FULL, u, 0);                              \
            acc += __logf(cn);                                               \
            u *= __fdividef(1.f, cn);                                        \
        }                                                                    \
        _Pragma("unroll")                                                    \
        for (int k = 0; k < 10; k++)                                         \
            v2[k] = pk2(__shfl_sync(FULL, u, 2 * k),                         \
                        __shfl_sync(FULL, u, 2 * k + 1));                    \
        v2[10] = pk2(__shfl_sync(FULL, u, 20), 0.f);                         \
    } while (0)

        int t = 1;
        const int nFull = (L - 1) >> 3;
        for (int it = 0; it < nFull; it++) {
            CRF_STEP(t + 0, 0);
            CRF_STEP(t + 1, 0);
            CRF_STEP(t + 2, 0);
            CRF_STEP(t + 3, 0);
            CRF_STEP(t + 4, 0);
            CRF_STEP(t + 5, 0);
            CRF_STEP(t + 6, 0);
            CRF_STEP(t + 7, 1);
            t += 8;
        }
        for (; t < L; t++) CRF_STEP(t, 0);

        float vlo, vhi;
        upk2(v2[j >> 1], vlo, vhi);
        float vf = (j & 1) ? vhi : vlo;
        float z = vf * eend;
#pragma unroll
        for (int o = 16; o; o >>= 1) z += __shfl_xor_sync(FULL, z, o);
        logZ = acc + __logf(z);
    }

    __syncthreads();
    if (tid == 0) g_llh[b] = sNum - logZ;
}

__global__ void reduce_kernel(float* __restrict__ out_loss)
{
    const int lane = threadIdx.x;   // 64 threads
    __shared__ float sp[2];
    float v = g_llh[lane];
#pragma unroll
    for (int o = 16; o; o >>= 1) v += __shfl_xor_sync(0xffffffffu, v, o);
    if ((lane & 31) == 0) sp[lane >> 5] = v;
    __syncthreads();
    if (lane == 0) out_loss[0] = -(sp[0] + sp[1]) / (float)B_;
}

// ---------------- launch ----------------

extern "C" void kernel_launch(void* const* d_in, const int* in_sizes, int n_in,
                              void* d_out, int out_size)
{
    const float* hs     = (const float*)d_in[0];
    const float* W      = (const float*)d_in[1];
    const float* bias   = (const float*)d_in[2];
    const float* trans  = (const float*)d_in[3];
    const float* startT = (const float*)d_in[4];
    const float* endT   = (const float*)d_in[5];
    const int*   att    = (const int*)d_in[6];
    const int*   labels = (const int*)d_in[7];
    float* out = (float*)d_out;

    cudaFuncSetAttribute(gemm_mma, cudaFuncAttributeMaxDynamicSharedMemorySize,
                         SMEM_B_BYTES);

    gemm_mma<<<256, 256, SMEM_B_BYTES>>>(hs, W, bias, out);
    crf_kernel<<<B_, 128>>>(out, trans, startT, endT, att, labels);
    reduce_kernel<<<1, 64>>>(out + (out_size - 1));
}